// round 15
// baseline (speedup 1.0000x reference)
#include <cuda_runtime.h>
#include <math.h>

#define BATCH 4
#define NC 16
#define NF 64
#define VV 262144
#define TOPK 100
#define CAND_MAX 4096
#define CANDS 2048
#define NBINS 65536
#define THETA 0.9f
#define INV_TAU 10.0f

#define GB 1024    // kB blocks
#define GLAB 1024  // kLab blocks
#define GA2 1024   // kA2 blocks: 8192 warps = 64 features x 128 slices

// ---------------- scratch (device globals; no allocations allowed) ----------------
__device__ float    g_weights[BATCH * VV];        // 4 MB
__device__ unsigned g_hist[BATCH * NBINS];        // 1 MB
__device__ unsigned g_labp[BATCH * VV / 4];       // 1 MB: 4 labels/word (1 byte each)
__device__ float    g_sums[NC * NF];
__device__ int      g_cnt[NC];
__device__ int      g_thresh[BATCH];
__device__ unsigned g_ccnt[BATCH];
__device__ float    g_cand_val[BATCH * CAND_MAX];
__device__ int      g_cand_idx[BATCH * CAND_MAX];

// ---------------- init: zero all accumulators + output ----------------------------
__global__ void kInit(float* out) {
    int gid = blockIdx.x * blockDim.x + threadIdx.x;   // 65536 threads
    ((uint4*)g_hist)[gid] = make_uint4(0u, 0u, 0u, 0u);
    if (gid < NC * NF) g_sums[gid] = 0.f;
    if (gid < NC)      g_cnt[gid] = 0;
    if (gid < BATCH)   g_ccnt[gid] = 0u;
    if (gid == 0)      out[0] = 0.f;
}

// ---------------- kLab: labels from one-hot y, packed 4/word + class counts -------
__global__ void kLab(const float* __restrict__ y) {
    __shared__ int s_cnt[NC];
    int tid = threadIdx.x;
    if (tid < NC) s_cnt[tid] = 0;
    __syncthreads();

    int gid = blockIdx.x * 256 + tid;      // 0..262143
    int b = gid >> 16;
    int r = gid & 65535;
    const float4* yp = (const float4*)(y + ((size_t)b * NC << 18)) + r;
    unsigned packed = 0;
    #pragma unroll
    for (int c = 0; c < NC; c++) {
        float4 yv = yp[(size_t)c * (VV / 4)];
        if (yv.x > 0.5f) packed |= (unsigned)c;
        if (yv.y > 0.5f) packed |= (unsigned)c << 8;
        if (yv.z > 0.5f) packed |= (unsigned)c << 16;
        if (yv.w > 0.5f) packed |= (unsigned)c << 24;
    }
    g_labp[gid] = packed;
    atomicAdd(&s_cnt[packed & 15], 1);
    atomicAdd(&s_cnt[(packed >> 8) & 15], 1);
    atomicAdd(&s_cnt[(packed >> 16) & 15], 1);
    atomicAdd(&s_cnt[(packed >> 24) & 15], 1);
    __syncthreads();
    if (tid < NC) atomicAdd(&g_cnt[tid], s_cnt[tid]);
}

// ---------------- kA2: per-class feature sums, barrier-free, 2 RMW chains ---------
// Warp W owns feature f = W & 63 and voxel slice sl = W >> 6 (128 slices of 8192).
// Lane l owns column l of BOTH tables: bank = lane, conflict-free, no cross-lane deps.
// x,y accumulate into T0; z,w into T1 -> two independent alias-chains.
__global__ void __launch_bounds__(256) kA2(const float* __restrict__ emb) {
    __shared__ float tab[8][2][NC * 32];   // 32 KB
    int tid = threadIdx.x, w = tid >> 5, lane = tid & 31;
    float* T0 = tab[w][0];
    float* T1 = tab[w][1];

    #pragma unroll
    for (int i = lane; i < NC * 32; i += 32) { T0[i] = 0.f; T1[i] = 0.f; }

    int W  = blockIdx.x * 8 + w;        // 0..8191
    int f  = W & 63;
    int sl = W >> 6;                    // 0..127
    int b  = sl >> 5;                   // 32 slices per batch
    int v4s = (sl & 31) << 11;          // slice start in float4 units (8192/4)

    const float4*   e4 = (const float4*)(emb) + ((size_t)(b * NF + f) << 16) + v4s;
    const unsigned* lp = g_labp + ((size_t)b << 16) + v4s;

    #pragma unroll 2
    for (int it = 0; it < 64; it++) {
        int idx = it * 32 + lane;
        float4 ev = e4[idx];
        unsigned l4 = lp[idx];
        T0[((l4      ) & 15) * 32 + lane] += ev.x;
        T0[((l4 >>  8) & 15) * 32 + lane] += ev.y;
        T1[((l4 >> 16) & 15) * 32 + lane] += ev.z;
        T1[((l4 >> 24) & 15) * 32 + lane] += ev.w;
    }

    // reduce each class row across lanes, flush to global
    #pragma unroll
    for (int c = 0; c < NC; c++) {
        float v = T0[c * 32 + lane] + T1[c * 32 + lane];
        v += __shfl_xor_sync(~0u, v, 16);
        v += __shfl_xor_sync(~0u, v, 8);
        v += __shfl_xor_sync(~0u, v, 4);
        v += __shfl_xor_sync(~0u, v, 2);
        v += __shfl_xor_sync(~0u, v, 1);
        if (lane == 0) atomicAdd(&g_sums[c * NF + f], v);
    }
}

// ---------------- kB: weights = prod_c proba + 16-bit key histogram ---------------
__global__ void kB(const float* __restrict__ proba) {
    int gid = blockIdx.x * 256 + threadIdx.x;   // 0..262143
    int b = gid >> 16;
    int r = gid & 65535;
    int v0 = r << 2;
    const float4* p4 = (const float4*)(proba + ((size_t)b * NC << 18) + v0);
    float4 acc = make_float4(1.f, 1.f, 1.f, 1.f);
    #pragma unroll
    for (int c = 0; c < NC; c++) {
        float4 p = p4[(size_t)c * (VV / 4)];
        acc.x *= p.x; acc.y *= p.y; acc.z *= p.z; acc.w *= p.w;
    }
    *(float4*)(g_weights + ((size_t)b << 18) + v0) = acc;
    unsigned base = (unsigned)b << 16;
    atomicAdd(&g_hist[base | (__float_as_uint(acc.x) >> 16)], 1u);
    atomicAdd(&g_hist[base | (__float_as_uint(acc.y) >> 16)], 1u);
    atomicAdd(&g_hist[base | (__float_as_uint(acc.z) >> 16)], 1u);
    atomicAdd(&g_hist[base | (__float_as_uint(acc.w) >> 16)], 1u);
}

// ---------------- kThresh: radix-select threshold key, 1024 threads/batch --------
__global__ void __launch_bounds__(1024) kThresh() {
    int b = blockIdx.x, t = threadIdx.x;    // 1024 threads
    const uint4* h4 = (const uint4*)(g_hist + b * NBINS);

    unsigned s = 0;
    #pragma unroll
    for (int i = 0; i < 16; i++) {
        uint4 v = h4[t * 16 + i];   // bins [64t, 64t+64)
        s += v.x + v.y + v.z + v.w;
    }

    __shared__ unsigned suf[1025];
    suf[t] = s;
    if (t == 0) suf[1024] = 0;
    __syncthreads();

    #pragma unroll
    for (int off = 1; off < 1024; off <<= 1) {
        unsigned add = (t + off < 1024) ? suf[t + off] : 0u;
        __syncthreads();
        suf[t] += add;
        __syncthreads();
    }

    if (suf[t] >= TOPK && suf[t + 1] < TOPK) {
        unsigned run = suf[t + 1];
        const unsigned* h = g_hist + b * NBINS + t * 64;
        int T = t * 64;
        for (int i = 63; i >= 0; i--) {
            run += h[i];
            if (run >= TOPK) { T = t * 64 + i; break; }
        }
        g_thresh[b] = T;
    }
}

// ---------------- kCollect: candidates >= threshold (vectorized) -----------------
__global__ void kCollect() {
    int gid = blockIdx.x * 256 + threadIdx.x;   // 262144
    int b = gid >> 16;
    int r = gid & 65535;
    int v0 = r << 2;
    float4 w4 = *(const float4*)(g_weights + ((size_t)b << 18) + v0);
    int th = g_thresh[b];
    float wv[4] = {w4.x, w4.y, w4.z, w4.w};
    #pragma unroll
    for (int k = 0; k < 4; k++) {
        if ((int)(__float_as_uint(wv[k]) >> 16) >= th) {
            unsigned pos = atomicAdd(&g_ccnt[b], 1u);
            if (pos < CAND_MAX) {
                g_cand_val[b * CAND_MAX + pos] = wv[k];
                g_cand_idx[b * CAND_MAX + pos] = v0 + k;
            }
        }
    }
}

// ---------------- kLossSel: top-100 rank + contrastive loss, block per (b,class) --
#define FCH 32
__global__ void kLossSel(const float* __restrict__ emb, float* out) {
    int b  = blockIdx.x >> 4;
    int cc = blockIdx.x & 15;
    int tid = threadIdx.x;   // 256

    __shared__ float s_val[CANDS];       // 8 KB
    __shared__ int   s_idx[CANDS];       // 8 KB
    __shared__ int   s_top[TOPK];
    __shared__ int   s_labk[TOPK];
    __shared__ float s_l[TOPK * FCH];    // 12.8 KB
    __shared__ float s_N[TOPK * FCH];    // 12.8 KB
    __shared__ float s_avg[NC * NF];     // 4 KB
    __shared__ int   s_mem[TOPK];
    __shared__ int   s_m;
    __shared__ float s_red[256];

    int n = min((int)g_ccnt[b], CANDS);
    for (int i = tid; i < n; i += 256) {
        s_val[i] = g_cand_val[b * CAND_MAX + i];
        s_idx[i] = g_cand_idx[b * CAND_MAX + i];
    }
    for (int i = tid; i < NC * NF; i += 256) {
        int c = i >> 6;
        int cnt = g_cnt[c];
        float mean = g_sums[i] / (float)max(cnt, 1);
        s_avg[i] = (cnt > 0) ? THETA * mean : 0.f;
    }
    __syncthreads();

    // exact top-100 by rank (jax tie-break: value desc, index asc)
    for (int i = tid; i < n; i += 256) {
        float vi = s_val[i]; int ii = s_idx[i];
        int rank = 0;
        for (int j = 0; j < n; j++) {
            float vj = s_val[j];
            rank += (vj > vi) || (vj == vi && s_idx[j] < ii);
        }
        if (rank < TOPK) s_top[rank] = ii;
    }
    __syncthreads();

    // labels of selected voxels (from packed label array)
    for (int k = tid; k < TOPK; k += 256) {
        int idx = s_top[k];
        unsigned lw = g_labp[((size_t)b << 16) + (idx >> 2)];
        s_labk[k] = (lw >> ((idx & 3) * 8)) & 15;
    }
    __syncthreads();

    // deterministic member compaction for class cc
    for (int k = tid; k < TOPK; k += 256) {
        if (s_labk[k] == cc) {
            int pos = 0;
            for (int kk = 0; kk < k; kk++) pos += (s_labk[kk] == cc);
            s_mem[pos] = s_top[k];   // voxel index
        }
    }
    if (tid == 0) {
        int mm = 0;
        for (int kk = 0; kk < TOPK; kk++) mm += (s_labk[kk] == cc);
        s_m = mm;
    }
    __syncthreads();
    int m = s_m;
    if (m == 0) return;   // uniform exit

    float local = 0.f;
    int npairs = m * m;

    #pragma unroll
    for (int fc = 0; fc < NF / FCH; fc++) {
        int f0 = fc * FCH;

        for (int q = tid; q < m * FCH; q += 256) {
            int j = q >> 5, ff = (q & (FCH - 1)) + f0;
            float he = emb[((size_t)b * NF + ff) * VV + s_mem[j]];
            float S = 0.f, lc = 0.f, ec = 1.f;
            #pragma unroll
            for (int c2 = 0; c2 < NC; c2++) {
                float l = he * s_avg[c2 * NF + ff] * INV_TAU;
                float e = expf(l);
                S += e;
                if (c2 == cc) { lc = l; ec = e; }
            }
            s_l[q] = lc;
            s_N[q] = S - ec;
        }
        __syncthreads();

        for (int pp = tid; pp < npairs; pp += 256) {
            int i = pp / m;
            int j = pp - i * m;
            const float* li = s_l + i * FCH;
            const float* Nj = s_N + j * FCH;
            #pragma unroll 8
            for (int ff = 0; ff < FCH; ff++) {
                float l = li[ff];
                local += logf(expf(l) + Nj[ff]) - l;
            }
        }
        __syncthreads();
    }

    s_red[tid] = local;
    __syncthreads();
    for (int s = 128; s > 0; s >>= 1) {
        if (tid < s) s_red[tid] += s_red[tid + s];
        __syncthreads();
    }
    if (tid == 0) {
        float denom = (float)m * (float)m * (float)NF;
        atomicAdd(out, -(s_red[0] / denom) / (float)BATCH);
    }
}

// ---------------- stream/event side resources (host objects, created pre-main) ----
struct ForkRes {
    cudaStream_t s2;
    cudaEvent_t  evI, evC;
    ForkRes() {
        cudaStreamCreateWithFlags(&s2, cudaStreamNonBlocking);
        cudaEventCreateWithFlags(&evI, cudaEventDisableTiming);
        cudaEventCreateWithFlags(&evC, cudaEventDisableTiming);
    }
};
static ForkRes g_fork;

// ---------------- launch (issue order puts kA2 at #4 for the ncu window) ----------
extern "C" void kernel_launch(void* const* d_in, const int* in_sizes, int n_in,
                              void* d_out, int out_size) {
    const float* proba = (const float*)d_in[0];
    const float* y     = (const float*)d_in[1];
    const float* emb   = (const float*)d_in[2];
    float* out = (float*)d_out;
    (void)in_sizes; (void)n_in; (void)out_size;

    kInit<<<256, 256>>>(out);                       // #1
    cudaEventRecord(g_fork.evI, 0);

    kLab<<<GLAB, 256>>>(y);                         // #2 (main)

    cudaStreamWaitEvent(g_fork.s2, g_fork.evI, 0);
    kB<<<GB, 256, 0, g_fork.s2>>>(proba);           // #3 (side)

    kA2<<<GA2, 256>>>(emb);                         // #4 (main) <- profiled

    kThresh<<<BATCH, 1024, 0, g_fork.s2>>>();       // #5 (side)
    kCollect<<<1024, 256, 0, g_fork.s2>>>();        // #6 (side)
    cudaEventRecord(g_fork.evC, g_fork.s2);

    // join: loss needs kA2 sums + labels + collected candidates
    cudaStreamWaitEvent(0, g_fork.evC, 0);
    kLossSel<<<BATCH * NC, 256>>>(emb, out);        // #7
}

// round 16
// speedup vs baseline: 1.2414x; 1.2414x over previous
#include <cuda_runtime.h>
#include <math.h>

#define BATCH 4
#define NC 16
#define NF 64
#define VV 262144
#define TOPK 100
#define CAND_MAX 4096
#define CANDS 2048
#define NBINS 65536
#define THETA 0.9f
#define INV_TAU 10.0f

#define GB 1024    // kB blocks
#define GLAB 1024  // kLab blocks
#define GA2 1024   // kA2 blocks: 8192 warps = 64 features x 128 slices

// ---------------- scratch (device globals; no allocations allowed) ----------------
__device__ float    g_weights[BATCH * VV];        // 4 MB
__device__ unsigned g_hist[BATCH * NBINS];        // 1 MB
__device__ unsigned g_labp[BATCH * VV / 4];       // 1 MB: 4 labels/word (1 byte each)
__device__ float    g_sums[NC * NF];
__device__ int      g_cnt[NC];
__device__ int      g_thresh[BATCH];
__device__ unsigned g_ccnt[BATCH];
__device__ float    g_cand_val[BATCH * CAND_MAX];
__device__ int      g_cand_idx[BATCH * CAND_MAX];

// ---------------- init: zero all accumulators + output ----------------------------
__global__ void kInit(float* out) {
    int gid = blockIdx.x * blockDim.x + threadIdx.x;   // 65536 threads
    ((uint4*)g_hist)[gid] = make_uint4(0u, 0u, 0u, 0u);
    if (gid < NC * NF) g_sums[gid] = 0.f;
    if (gid < NC)      g_cnt[gid] = 0;
    if (gid < BATCH)   g_ccnt[gid] = 0u;
    if (gid == 0)      out[0] = 0.f;
}

// ---------------- kLab: labels from one-hot y, packed 4/word + class counts -------
__global__ void kLab(const float* __restrict__ y) {
    __shared__ int s_cnt[NC];
    int tid = threadIdx.x;
    if (tid < NC) s_cnt[tid] = 0;
    __syncthreads();

    int gid = blockIdx.x * 256 + tid;      // 0..262143
    int b = gid >> 16;
    int r = gid & 65535;
    const float4* yp = (const float4*)(y + ((size_t)b * NC << 18)) + r;
    unsigned packed = 0;
    #pragma unroll
    for (int c = 0; c < NC; c++) {
        float4 yv = yp[(size_t)c * (VV / 4)];
        if (yv.x > 0.5f) packed |= (unsigned)c;
        if (yv.y > 0.5f) packed |= (unsigned)c << 8;
        if (yv.z > 0.5f) packed |= (unsigned)c << 16;
        if (yv.w > 0.5f) packed |= (unsigned)c << 24;
    }
    g_labp[gid] = packed;
    atomicAdd(&s_cnt[packed & 15], 1);
    atomicAdd(&s_cnt[(packed >> 8) & 15], 1);
    atomicAdd(&s_cnt[(packed >> 16) & 15], 1);
    atomicAdd(&s_cnt[(packed >> 24) & 15], 1);
    __syncthreads();
    if (tid < NC) atomicAdd(&g_cnt[tid], s_cnt[tid]);
}

// ---------------- kA2: per-class feature sums, barrier-free, MLP=8 ----------------
// Warp W owns feature f = W & 63 and voxel slice sl = W >> 6 (128 slices of 8192).
// Lane l owns table column l: bank = lane, conflict-free RMW, no cross-lane deps.
// Unroll-4 with ALL loads issued before any RMW -> 8 outstanding LDGs per warp.
__global__ void __launch_bounds__(256, 6) kA2(const float* __restrict__ emb) {
    __shared__ float tab[8][NC * 32];   // 16 KB, per-warp tables
    int tid = threadIdx.x, w = tid >> 5, lane = tid & 31;
    float* T = tab[w];

    #pragma unroll
    for (int i = lane; i < NC * 32; i += 32) T[i] = 0.f;   // own column only

    int W  = blockIdx.x * 8 + w;        // 0..8191
    int f  = W & 63;
    int sl = W >> 6;                    // 0..127
    int b  = sl >> 5;                   // 32 slices per batch
    int v4s = (sl & 31) << 11;          // slice start in float4 units (8192/4)

    const float4*   e4 = (const float4*)(emb) + ((size_t)(b * NF + f) << 16) + v4s + lane;
    const unsigned* lp = g_labp + ((size_t)b << 16) + v4s + lane;

    for (int it = 0; it < 64; it += 4) {
        // front-batched loads: 8 outstanding before first dependent use
        float4 ev0 = e4[(it + 0) * 32];
        float4 ev1 = e4[(it + 1) * 32];
        float4 ev2 = e4[(it + 2) * 32];
        float4 ev3 = e4[(it + 3) * 32];
        unsigned a0 = lp[(it + 0) * 32];
        unsigned a1 = lp[(it + 1) * 32];
        unsigned a2 = lp[(it + 2) * 32];
        unsigned a3 = lp[(it + 3) * 32];

        T[((a0      ) & 15) * 32 + lane] += ev0.x;
        T[((a0 >>  8) & 15) * 32 + lane] += ev0.y;
        T[((a0 >> 16) & 15) * 32 + lane] += ev0.z;
        T[((a0 >> 24) & 15) * 32 + lane] += ev0.w;
        T[((a1      ) & 15) * 32 + lane] += ev1.x;
        T[((a1 >>  8) & 15) * 32 + lane] += ev1.y;
        T[((a1 >> 16) & 15) * 32 + lane] += ev1.z;
        T[((a1 >> 24) & 15) * 32 + lane] += ev1.w;
        T[((a2      ) & 15) * 32 + lane] += ev2.x;
        T[((a2 >>  8) & 15) * 32 + lane] += ev2.y;
        T[((a2 >> 16) & 15) * 32 + lane] += ev2.z;
        T[((a2 >> 24) & 15) * 32 + lane] += ev2.w;
        T[((a3      ) & 15) * 32 + lane] += ev3.x;
        T[((a3 >>  8) & 15) * 32 + lane] += ev3.y;
        T[((a3 >> 16) & 15) * 32 + lane] += ev3.z;
        T[((a3 >> 24) & 15) * 32 + lane] += ev3.w;
    }

    // reduce each class row across lanes, flush to global
    #pragma unroll
    for (int c = 0; c < NC; c++) {
        float v = T[c * 32 + lane];
        v += __shfl_xor_sync(~0u, v, 16);
        v += __shfl_xor_sync(~0u, v, 8);
        v += __shfl_xor_sync(~0u, v, 4);
        v += __shfl_xor_sync(~0u, v, 2);
        v += __shfl_xor_sync(~0u, v, 1);
        if (lane == 0) atomicAdd(&g_sums[c * NF + f], v);
    }
}

// ---------------- kB: weights = prod_c proba + 16-bit key histogram ---------------
__global__ void kB(const float* __restrict__ proba) {
    int gid = blockIdx.x * 256 + threadIdx.x;   // 0..262143
    int b = gid >> 16;
    int r = gid & 65535;
    int v0 = r << 2;
    const float4* p4 = (const float4*)(proba + ((size_t)b * NC << 18) + v0);
    float4 acc = make_float4(1.f, 1.f, 1.f, 1.f);
    #pragma unroll
    for (int c = 0; c < NC; c++) {
        float4 p = p4[(size_t)c * (VV / 4)];
        acc.x *= p.x; acc.y *= p.y; acc.z *= p.z; acc.w *= p.w;
    }
    *(float4*)(g_weights + ((size_t)b << 18) + v0) = acc;
    unsigned base = (unsigned)b << 16;
    atomicAdd(&g_hist[base | (__float_as_uint(acc.x) >> 16)], 1u);
    atomicAdd(&g_hist[base | (__float_as_uint(acc.y) >> 16)], 1u);
    atomicAdd(&g_hist[base | (__float_as_uint(acc.z) >> 16)], 1u);
    atomicAdd(&g_hist[base | (__float_as_uint(acc.w) >> 16)], 1u);
}

// ---------------- kThresh: radix-select threshold key, 1024 threads/batch --------
__global__ void __launch_bounds__(1024) kThresh() {
    int b = blockIdx.x, t = threadIdx.x;    // 1024 threads
    const uint4* h4 = (const uint4*)(g_hist + b * NBINS);

    unsigned s = 0;
    #pragma unroll
    for (int i = 0; i < 16; i++) {
        uint4 v = h4[t * 16 + i];   // bins [64t, 64t+64)
        s += v.x + v.y + v.z + v.w;
    }

    __shared__ unsigned suf[1025];
    suf[t] = s;
    if (t == 0) suf[1024] = 0;
    __syncthreads();

    #pragma unroll
    for (int off = 1; off < 1024; off <<= 1) {
        unsigned add = (t + off < 1024) ? suf[t + off] : 0u;
        __syncthreads();
        suf[t] += add;
        __syncthreads();
    }

    if (suf[t] >= TOPK && suf[t + 1] < TOPK) {
        unsigned run = suf[t + 1];
        const unsigned* h = g_hist + b * NBINS + t * 64;
        int T = t * 64;
        for (int i = 63; i >= 0; i--) {
            run += h[i];
            if (run >= TOPK) { T = t * 64 + i; break; }
        }
        g_thresh[b] = T;
    }
}

// ---------------- kCollect: candidates >= threshold (vectorized) -----------------
__global__ void kCollect() {
    int gid = blockIdx.x * 256 + threadIdx.x;   // 262144
    int b = gid >> 16;
    int r = gid & 65535;
    int v0 = r << 2;
    float4 w4 = *(const float4*)(g_weights + ((size_t)b << 18) + v0);
    int th = g_thresh[b];
    float wv[4] = {w4.x, w4.y, w4.z, w4.w};
    #pragma unroll
    for (int k = 0; k < 4; k++) {
        if ((int)(__float_as_uint(wv[k]) >> 16) >= th) {
            unsigned pos = atomicAdd(&g_ccnt[b], 1u);
            if (pos < CAND_MAX) {
                g_cand_val[b * CAND_MAX + pos] = wv[k];
                g_cand_idx[b * CAND_MAX + pos] = v0 + k;
            }
        }
    }
}

// ---------------- kLossSel: top-100 rank + contrastive loss, block per (b,class) --
#define FCH 32
__global__ void kLossSel(const float* __restrict__ emb, float* out) {
    int b  = blockIdx.x >> 4;
    int cc = blockIdx.x & 15;
    int tid = threadIdx.x;   // 256

    __shared__ float s_val[CANDS];       // 8 KB
    __shared__ int   s_idx[CANDS];       // 8 KB
    __shared__ int   s_top[TOPK];
    __shared__ int   s_labk[TOPK];
    __shared__ float s_l[TOPK * FCH];    // 12.8 KB
    __shared__ float s_N[TOPK * FCH];    // 12.8 KB
    __shared__ float s_avg[NC * NF];     // 4 KB
    __shared__ int   s_mem[TOPK];
    __shared__ int   s_m;
    __shared__ float s_red[256];

    int n = min((int)g_ccnt[b], CANDS);
    for (int i = tid; i < n; i += 256) {
        s_val[i] = g_cand_val[b * CAND_MAX + i];
        s_idx[i] = g_cand_idx[b * CAND_MAX + i];
    }
    for (int i = tid; i < NC * NF; i += 256) {
        int c = i >> 6;
        int cnt = g_cnt[c];
        float mean = g_sums[i] / (float)max(cnt, 1);
        s_avg[i] = (cnt > 0) ? THETA * mean : 0.f;
    }
    __syncthreads();

    // exact top-100 by rank (jax tie-break: value desc, index asc)
    for (int i = tid; i < n; i += 256) {
        float vi = s_val[i]; int ii = s_idx[i];
        int rank = 0;
        for (int j = 0; j < n; j++) {
            float vj = s_val[j];
            rank += (vj > vi) || (vj == vi && s_idx[j] < ii);
        }
        if (rank < TOPK) s_top[rank] = ii;
    }
    __syncthreads();

    // labels of selected voxels (from packed label array)
    for (int k = tid; k < TOPK; k += 256) {
        int idx = s_top[k];
        unsigned lw = g_labp[((size_t)b << 16) + (idx >> 2)];
        s_labk[k] = (lw >> ((idx & 3) * 8)) & 15;
    }
    __syncthreads();

    // deterministic member compaction for class cc
    for (int k = tid; k < TOPK; k += 256) {
        if (s_labk[k] == cc) {
            int pos = 0;
            for (int kk = 0; kk < k; kk++) pos += (s_labk[kk] == cc);
            s_mem[pos] = s_top[k];   // voxel index
        }
    }
    if (tid == 0) {
        int mm = 0;
        for (int kk = 0; kk < TOPK; kk++) mm += (s_labk[kk] == cc);
        s_m = mm;
    }
    __syncthreads();
    int m = s_m;
    if (m == 0) return;   // uniform exit

    float local = 0.f;
    int npairs = m * m;

    #pragma unroll
    for (int fc = 0; fc < NF / FCH; fc++) {
        int f0 = fc * FCH;

        for (int q = tid; q < m * FCH; q += 256) {
            int j = q >> 5, ff = (q & (FCH - 1)) + f0;
            float he = emb[((size_t)b * NF + ff) * VV + s_mem[j]];
            float S = 0.f, lc = 0.f, ec = 1.f;
            #pragma unroll
            for (int c2 = 0; c2 < NC; c2++) {
                float l = he * s_avg[c2 * NF + ff] * INV_TAU;
                float e = expf(l);
                S += e;
                if (c2 == cc) { lc = l; ec = e; }
            }
            s_l[q] = lc;
            s_N[q] = S - ec;
        }
        __syncthreads();

        for (int pp = tid; pp < npairs; pp += 256) {
            int i = pp / m;
            int j = pp - i * m;
            const float* li = s_l + i * FCH;
            const float* Nj = s_N + j * FCH;
            #pragma unroll 8
            for (int ff = 0; ff < FCH; ff++) {
                float l = li[ff];
                local += logf(expf(l) + Nj[ff]) - l;
            }
        }
        __syncthreads();
    }

    s_red[tid] = local;
    __syncthreads();
    for (int s = 128; s > 0; s >>= 1) {
        if (tid < s) s_red[tid] += s_red[tid + s];
        __syncthreads();
    }
    if (tid == 0) {
        float denom = (float)m * (float)m * (float)NF;
        atomicAdd(out, -(s_red[0] / denom) / (float)BATCH);
    }
}

// ---------------- stream/event side resources (host objects, created pre-main) ----
struct ForkRes {
    cudaStream_t s2;
    cudaEvent_t  evI, evC;
    ForkRes() {
        cudaStreamCreateWithFlags(&s2, cudaStreamNonBlocking);
        cudaEventCreateWithFlags(&evI, cudaEventDisableTiming);
        cudaEventCreateWithFlags(&evC, cudaEventDisableTiming);
    }
};
static ForkRes g_fork;

// ---------------- launch (r14 issue order: side chain issued before kA2) ----------
extern "C" void kernel_launch(void* const* d_in, const int* in_sizes, int n_in,
                              void* d_out, int out_size) {
    const float* proba = (const float*)d_in[0];
    const float* y     = (const float*)d_in[1];
    const float* emb   = (const float*)d_in[2];
    float* out = (float*)d_out;
    (void)in_sizes; (void)n_in; (void)out_size;

    kInit<<<256, 256>>>(out);

    // fork after init: the kB chain runs beside kLab+kA2
    cudaEventRecord(g_fork.evI, 0);
    cudaStreamWaitEvent(g_fork.s2, g_fork.evI, 0);
    kB<<<GB, 256, 0, g_fork.s2>>>(proba);
    kThresh<<<BATCH, 1024, 0, g_fork.s2>>>();
    kCollect<<<1024, 256, 0, g_fork.s2>>>();
    cudaEventRecord(g_fork.evC, g_fork.s2);

    kLab<<<GLAB, 256>>>(y);
    kA2<<<GA2, 256>>>(emb);

    // join: loss needs kA2 sums + labels + collected candidates
    cudaStreamWaitEvent(0, g_fork.evC, 0);
    kLossSel<<<BATCH * NC, 256>>>(emb, out);
}

// round 17
// speedup vs baseline: 1.2893x; 1.0386x over previous
#include <cuda_runtime.h>
#include <math.h>

#define BATCH 4
#define NC 16
#define NF 64
#define VV 262144
#define TOPK 100
#define CAND_MAX 4096
#define CANDS 2048
#define NBINS 65536
#define THETA 0.9f
#define INV_TAU 10.0f

#define GB 1024     // kB blocks
#define GLAB 1024   // label-role blocks in kFused
#define GA2 1024    // accum-role blocks in kFused
#define NSLICE 128  // 8192-voxel slices across all batches

// ---------------- scratch (device globals; no allocations allowed) ----------------
__device__ float    g_weights[BATCH * VV];        // 4 MB
__device__ unsigned g_hist[BATCH * NBINS];        // 1 MB
__device__ unsigned g_labp[BATCH * VV / 4];       // 1 MB: 4 labels/word
__device__ int      g_flag[NSLICE];               // per-slice ready counters
__device__ float    g_sums[NC * NF];
__device__ int      g_cnt[NC];
__device__ int      g_thresh[BATCH];
__device__ unsigned g_ccnt[BATCH];
__device__ float    g_cand_val[BATCH * CAND_MAX];
__device__ int      g_cand_idx[BATCH * CAND_MAX];

// ---------------- init: zero all accumulators + output ----------------------------
__global__ void kInit(float* out) {
    int gid = blockIdx.x * blockDim.x + threadIdx.x;   // 65536 threads
    ((uint4*)g_hist)[gid] = make_uint4(0u, 0u, 0u, 0u);
    if (gid < NC * NF) g_sums[gid] = 0.f;
    if (gid < NC)      g_cnt[gid] = 0;
    if (gid < NSLICE)  g_flag[gid] = 0;
    if (gid < BATCH)   g_ccnt[gid] = 0u;
    if (gid == 0)      out[0] = 0.f;
}

// ---------------- kFused: label role (bids 0..1023) + accum role (1024..2047) -----
// Label block g covers labp words [g*256, g*256+256) = 1024 voxels = 1/8 of
// global slice (g>>3). After writing, fence + flag increment.
// Accum warp W owns feature f = W & 63, slice sl = W >> 6; spins until
// flag[sl] == 8, then accumulates with lane-owned conflict-free tables.
__global__ void __launch_bounds__(256) kFused(const float* __restrict__ y,
                                              const float* __restrict__ emb) {
    __shared__ float tab[8][NC * 32];   // 16 KB (accum role)
    __shared__ int   s_cnt[NC];         // (label role)
    int tid = threadIdx.x, w = tid >> 5, lane = tid & 31;
    int bid = blockIdx.x;

    if (bid < GLAB) {
        // ---- label role ----
        if (tid < NC) s_cnt[tid] = 0;
        __syncthreads();

        int gid = bid * 256 + tid;      // word index 0..262143
        int b = gid >> 16;
        int r = gid & 65535;
        const float4* yp = (const float4*)(y + ((size_t)b * NC << 18)) + r;
        unsigned packed = 0;
        #pragma unroll
        for (int c = 0; c < NC; c++) {
            float4 yv = yp[(size_t)c * (VV / 4)];
            if (yv.x > 0.5f) packed |= (unsigned)c;
            if (yv.y > 0.5f) packed |= (unsigned)c << 8;
            if (yv.z > 0.5f) packed |= (unsigned)c << 16;
            if (yv.w > 0.5f) packed |= (unsigned)c << 24;
        }
        g_labp[gid] = packed;
        atomicAdd(&s_cnt[packed & 15], 1);
        atomicAdd(&s_cnt[(packed >> 8) & 15], 1);
        atomicAdd(&s_cnt[(packed >> 16) & 15], 1);
        atomicAdd(&s_cnt[(packed >> 24) & 15], 1);
        __syncthreads();
        if (tid < NC) atomicAdd(&g_cnt[tid], s_cnt[tid]);

        // publish: this block's 256 labp words are globally visible
        __threadfence();
        if (tid == 0) atomicAdd(&g_flag[bid >> 3], 1);
        return;
    }

    // ---- accum role ----
    int W  = (bid - GLAB) * 8 + w;      // 0..8191
    int f  = W & 63;
    int sl = W >> 6;                    // 0..127 (global slice)
    int b  = sl >> 5;
    int v4s = (sl & 31) << 11;

    float* T = tab[w];
    #pragma unroll
    for (int i = lane; i < NC * 32; i += 32) T[i] = 0.f;   // own column only

    // wait until all 8 label blocks of this slice published
    if (tid == 0) {
        while (*((volatile int*)&g_flag[sl]) < 8) __nanosleep(64);
    }
    __syncthreads();
    __threadfence();   // acquire

    const float4*   e4 = (const float4*)(emb) + ((size_t)(b * NF + f) << 16) + v4s + lane;
    const unsigned* lp = g_labp + ((size_t)b << 16) + v4s + lane;

    for (int it = 0; it < 64; it += 4) {
        float4 ev0 = e4[(it + 0) * 32];
        float4 ev1 = e4[(it + 1) * 32];
        float4 ev2 = e4[(it + 2) * 32];
        float4 ev3 = e4[(it + 3) * 32];
        unsigned a0 = lp[(it + 0) * 32];
        unsigned a1 = lp[(it + 1) * 32];
        unsigned a2 = lp[(it + 2) * 32];
        unsigned a3 = lp[(it + 3) * 32];

        T[((a0      ) & 15) * 32 + lane] += ev0.x;
        T[((a0 >>  8) & 15) * 32 + lane] += ev0.y;
        T[((a0 >> 16) & 15) * 32 + lane] += ev0.z;
        T[((a0 >> 24) & 15) * 32 + lane] += ev0.w;
        T[((a1      ) & 15) * 32 + lane] += ev1.x;
        T[((a1 >>  8) & 15) * 32 + lane] += ev1.y;
        T[((a1 >> 16) & 15) * 32 + lane] += ev1.z;
        T[((a1 >> 24) & 15) * 32 + lane] += ev1.w;
        T[((a2      ) & 15) * 32 + lane] += ev2.x;
        T[((a2 >>  8) & 15) * 32 + lane] += ev2.y;
        T[((a2 >> 16) & 15) * 32 + lane] += ev2.z;
        T[((a2 >> 24) & 15) * 32 + lane] += ev2.w;
        T[((a3      ) & 15) * 32 + lane] += ev3.x;
        T[((a3 >>  8) & 15) * 32 + lane] += ev3.y;
        T[((a3 >> 16) & 15) * 32 + lane] += ev3.z;
        T[((a3 >> 24) & 15) * 32 + lane] += ev3.w;
    }

    // reduce each class row across lanes, flush to global
    #pragma unroll
    for (int c = 0; c < NC; c++) {
        float v = T[c * 32 + lane];
        v += __shfl_xor_sync(~0u, v, 16);
        v += __shfl_xor_sync(~0u, v, 8);
        v += __shfl_xor_sync(~0u, v, 4);
        v += __shfl_xor_sync(~0u, v, 2);
        v += __shfl_xor_sync(~0u, v, 1);
        if (lane == 0) atomicAdd(&g_sums[c * NF + f], v);
    }
}

// ---------------- kB: weights = prod_c proba + 16-bit key histogram ---------------
__global__ void kB(const float* __restrict__ proba) {
    int gid = blockIdx.x * 256 + threadIdx.x;   // 0..262143
    int b = gid >> 16;
    int r = gid & 65535;
    int v0 = r << 2;
    const float4* p4 = (const float4*)(proba + ((size_t)b * NC << 18) + v0);
    float4 acc = make_float4(1.f, 1.f, 1.f, 1.f);
    #pragma unroll
    for (int c = 0; c < NC; c++) {
        float4 p = p4[(size_t)c * (VV / 4)];
        acc.x *= p.x; acc.y *= p.y; acc.z *= p.z; acc.w *= p.w;
    }
    *(float4*)(g_weights + ((size_t)b << 18) + v0) = acc;
    unsigned base = (unsigned)b << 16;
    atomicAdd(&g_hist[base | (__float_as_uint(acc.x) >> 16)], 1u);
    atomicAdd(&g_hist[base | (__float_as_uint(acc.y) >> 16)], 1u);
    atomicAdd(&g_hist[base | (__float_as_uint(acc.z) >> 16)], 1u);
    atomicAdd(&g_hist[base | (__float_as_uint(acc.w) >> 16)], 1u);
}

// ---------------- kThresh: radix-select threshold key, 1024 threads/batch --------
__global__ void __launch_bounds__(1024) kThresh() {
    int b = blockIdx.x, t = threadIdx.x;    // 1024 threads
    const uint4* h4 = (const uint4*)(g_hist + b * NBINS);

    unsigned s = 0;
    #pragma unroll
    for (int i = 0; i < 16; i++) {
        uint4 v = h4[t * 16 + i];   // bins [64t, 64t+64)
        s += v.x + v.y + v.z + v.w;
    }

    __shared__ unsigned suf[1025];
    suf[t] = s;
    if (t == 0) suf[1024] = 0;
    __syncthreads();

    #pragma unroll
    for (int off = 1; off < 1024; off <<= 1) {
        unsigned add = (t + off < 1024) ? suf[t + off] : 0u;
        __syncthreads();
        suf[t] += add;
        __syncthreads();
    }

    if (suf[t] >= TOPK && suf[t + 1] < TOPK) {
        unsigned run = suf[t + 1];
        const unsigned* h = g_hist + b * NBINS + t * 64;
        int T = t * 64;
        for (int i = 63; i >= 0; i--) {
            run += h[i];
            if (run >= TOPK) { T = t * 64 + i; break; }
        }
        g_thresh[b] = T;
    }
}

// ---------------- kCollect: candidates >= threshold (vectorized) -----------------
__global__ void kCollect() {
    int gid = blockIdx.x * 256 + threadIdx.x;   // 262144
    int b = gid >> 16;
    int r = gid & 65535;
    int v0 = r << 2;
    float4 w4 = *(const float4*)(g_weights + ((size_t)b << 18) + v0);
    int th = g_thresh[b];
    float wv[4] = {w4.x, w4.y, w4.z, w4.w};
    #pragma unroll
    for (int k = 0; k < 4; k++) {
        if ((int)(__float_as_uint(wv[k]) >> 16) >= th) {
            unsigned pos = atomicAdd(&g_ccnt[b], 1u);
            if (pos < CAND_MAX) {
                g_cand_val[b * CAND_MAX + pos] = wv[k];
                g_cand_idx[b * CAND_MAX + pos] = v0 + k;
            }
        }
    }
}

// ---------------- kLossSel: top-100 rank + contrastive loss, block per (b,class) --
#define FCH 32
__global__ void kLossSel(const float* __restrict__ emb, float* out) {
    int b  = blockIdx.x >> 4;
    int cc = blockIdx.x & 15;
    int tid = threadIdx.x;   // 256

    __shared__ float s_val[CANDS];       // 8 KB
    __shared__ int   s_idx[CANDS];       // 8 KB
    __shared__ int   s_top[TOPK];
    __shared__ int   s_labk[TOPK];
    __shared__ float s_l[TOPK * FCH];    // 12.8 KB
    __shared__ float s_N[TOPK * FCH];    // 12.8 KB
    __shared__ float s_avg[NC * NF];     // 4 KB
    __shared__ int   s_mem[TOPK];
    __shared__ int   s_m;
    __shared__ float s_red[256];

    int n = min((int)g_ccnt[b], CANDS);
    for (int i = tid; i < n; i += 256) {
        s_val[i] = g_cand_val[b * CAND_MAX + i];
        s_idx[i] = g_cand_idx[b * CAND_MAX + i];
    }
    for (int i = tid; i < NC * NF; i += 256) {
        int c = i >> 6;
        int cnt = g_cnt[c];
        float mean = g_sums[i] / (float)max(cnt, 1);
        s_avg[i] = (cnt > 0) ? THETA * mean : 0.f;
    }
    __syncthreads();

    // exact top-100 by rank (jax tie-break: value desc, index asc)
    for (int i = tid; i < n; i += 256) {
        float vi = s_val[i]; int ii = s_idx[i];
        int rank = 0;
        for (int j = 0; j < n; j++) {
            float vj = s_val[j];
            rank += (vj > vi) || (vj == vi && s_idx[j] < ii);
        }
        if (rank < TOPK) s_top[rank] = ii;
    }
    __syncthreads();

    // labels of selected voxels (from packed label array)
    for (int k = tid; k < TOPK; k += 256) {
        int idx = s_top[k];
        unsigned lw = g_labp[((size_t)b << 16) + (idx >> 2)];
        s_labk[k] = (lw >> ((idx & 3) * 8)) & 15;
    }
    __syncthreads();

    // deterministic member compaction for class cc
    for (int k = tid; k < TOPK; k += 256) {
        if (s_labk[k] == cc) {
            int pos = 0;
            for (int kk = 0; kk < k; kk++) pos += (s_labk[kk] == cc);
            s_mem[pos] = s_top[k];   // voxel index
        }
    }
    if (tid == 0) {
        int mm = 0;
        for (int kk = 0; kk < TOPK; kk++) mm += (s_labk[kk] == cc);
        s_m = mm;
    }
    __syncthreads();
    int m = s_m;
    if (m == 0) return;   // uniform exit

    float local = 0.f;
    int npairs = m * m;

    #pragma unroll
    for (int fc = 0; fc < NF / FCH; fc++) {
        int f0 = fc * FCH;

        for (int q = tid; q < m * FCH; q += 256) {
            int j = q >> 5, ff = (q & (FCH - 1)) + f0;
            float he = emb[((size_t)b * NF + ff) * VV + s_mem[j]];
            float S = 0.f, lc = 0.f, ec = 1.f;
            #pragma unroll
            for (int c2 = 0; c2 < NC; c2++) {
                float l = he * s_avg[c2 * NF + ff] * INV_TAU;
                float e = expf(l);
                S += e;
                if (c2 == cc) { lc = l; ec = e; }
            }
            s_l[q] = lc;
            s_N[q] = S - ec;
        }
        __syncthreads();

        for (int pp = tid; pp < npairs; pp += 256) {
            int i = pp / m;
            int j = pp - i * m;
            const float* li = s_l + i * FCH;
            const float* Nj = s_N + j * FCH;
            #pragma unroll 8
            for (int ff = 0; ff < FCH; ff++) {
                float l = li[ff];
                local += logf(expf(l) + Nj[ff]) - l;
            }
        }
        __syncthreads();
    }

    s_red[tid] = local;
    __syncthreads();
    for (int s = 128; s > 0; s >>= 1) {
        if (tid < s) s_red[tid] += s_red[tid + s];
        __syncthreads();
    }
    if (tid == 0) {
        float denom = (float)m * (float)m * (float)NF;
        atomicAdd(out, -(s_red[0] / denom) / (float)BATCH);
    }
}

// ---------------- stream/event side resources (host objects, created pre-main) ----
struct ForkRes {
    cudaStream_t s2;
    cudaEvent_t  evI, evC;
    ForkRes() {
        cudaStreamCreateWithFlags(&s2, cudaStreamNonBlocking);
        cudaEventCreateWithFlags(&evI, cudaEventDisableTiming);
        cudaEventCreateWithFlags(&evC, cudaEventDisableTiming);
    }
};
static ForkRes g_fork;

// ---------------- launch ----------------------------------------------------------
extern "C" void kernel_launch(void* const* d_in, const int* in_sizes, int n_in,
                              void* d_out, int out_size) {
    const float* proba = (const float*)d_in[0];
    const float* y     = (const float*)d_in[1];
    const float* emb   = (const float*)d_in[2];
    float* out = (float*)d_out;
    (void)in_sizes; (void)n_in; (void)out_size;

    kInit<<<256, 256>>>(out);

    // fork after init: kB chain runs beside kFused
    cudaEventRecord(g_fork.evI, 0);
    cudaStreamWaitEvent(g_fork.s2, g_fork.evI, 0);
    kB<<<GB, 256, 0, g_fork.s2>>>(proba);
    kThresh<<<BATCH, 1024, 0, g_fork.s2>>>();
    kCollect<<<1024, 256, 0, g_fork.s2>>>();
    cudaEventRecord(g_fork.evC, g_fork.s2);

    kFused<<<GLAB + GA2, 256>>>(y, emb);

    // join: loss needs sums + labels + collected candidates
    cudaStreamWaitEvent(0, g_fork.evC, 0);
    kLossSel<<<BATCH * NC, 256>>>(emb, out);
}